// round 2
// baseline (speedup 1.0000x reference)
#include <cuda_runtime.h>
#include <mma.h>
#include <math.h>

using namespace nvcuda;

#define N_NODES 50000
#define DMODEL  512
#define NH      8
#define HD      64
#define HIDDEN  1536

// ---------------- static device scratch (no allocs allowed) ----------------
// qkv buffer: q,k,v each [N,512]; reused as MLP hidden h [N,1536] (same size).
__device__ float g_qkv[(size_t)3 * N_NODES * DMODEL];
__device__ float g_xn [(size_t)N_NODES * DMODEL];
__device__ float g_attn[(size_t)N_NODES * DMODEL];

// ---------------- LayerNorm: one warp per row ----------------
__global__ void ln_kernel(const float* __restrict__ x, const float* __restrict__ g,
                          const float* __restrict__ b, float* __restrict__ y, int n)
{
    int row  = blockIdx.x * 8 + (threadIdx.x >> 5);
    int lane = threadIdx.x & 31;
    if (row >= n) return;
    const float4* xp = (const float4*)(x + (size_t)row * DMODEL);
    float4 v[4];
    float s = 0.f, ss = 0.f;
#pragma unroll
    for (int i = 0; i < 4; i++) {
        v[i] = xp[i * 32 + lane];
        s  += v[i].x + v[i].y + v[i].z + v[i].w;
        ss += v[i].x*v[i].x + v[i].y*v[i].y + v[i].z*v[i].z + v[i].w*v[i].w;
    }
#pragma unroll
    for (int o = 16; o; o >>= 1) {
        s  += __shfl_xor_sync(0xffffffffu, s,  o);
        ss += __shfl_xor_sync(0xffffffffu, ss, o);
    }
    float mean = s * (1.f / DMODEL);
    float var  = ss * (1.f / DMODEL) - mean * mean;
    float rs   = rsqrtf(var + 1e-5f);
    float4* yp = (float4*)(y + (size_t)row * DMODEL);
    const float4* gp = (const float4*)g;
    const float4* bp = (const float4*)b;
#pragma unroll
    for (int i = 0; i < 4; i++) {
        int c = i * 32 + lane;
        float4 gg = gp[c], bb = bp[c], xx = v[i], o4;
        o4.x = (xx.x - mean) * rs * gg.x + bb.x;
        o4.y = (xx.y - mean) * rs * gg.y + bb.y;
        o4.z = (xx.z - mean) * rs * gg.z + bb.z;
        o4.w = (xx.w - mean) * rs * gg.w + bb.w;
        yp[c] = o4;
    }
}

// ---------------- TF32 tensor-core GEMM: C[n,M] = A[n,K] @ B[K,M] + bias -----
// Tiles: 128x128 block, BK=16; 8 warps (2x4), each warp 64x32 = 4x2 wmma frags.
// EPI: 0 = bias only, 1 = gelu(bias), 2 = bias + residual (res may alias C)
template<int EPI>
__global__ void __launch_bounds__(256)
tf32gemm_kernel(const float* __restrict__ A, const float* __restrict__ B,
                const float* __restrict__ bias, const float* __restrict__ res,
                float* __restrict__ C, int n, int K, int M)
{
    constexpr int BM = 128, BN = 128, BK = 16;
    __shared__ float As[BM][BK + 4];      // stride 20 floats (80B, 16B-aligned rows)
    __shared__ float Bs[BK][BN + 4];      // stride 132 floats (528B, 16B-aligned)
    __shared__ float stage[8][16][20];    // per-warp epilogue staging

    int tid  = threadIdx.x;
    int w    = tid >> 5, lane = tid & 31;
    int wr   = w >> 2,   wc   = w & 3;    // warp grid 2 (rows) x 4 (cols)
    int rowBase = blockIdx.y * BM;
    int colBase = blockIdx.x * BN;

    wmma::fragment<wmma::accumulator, 16, 16, 8, float> acc[4][2];
#pragma unroll
    for (int i = 0; i < 4; i++)
#pragma unroll
        for (int j = 0; j < 2; j++) wmma::fill_fragment(acc[i][j], 0.f);

    for (int k0 = 0; k0 < K; k0 += BK) {
        // A tile: 128x16 floats = 512 float4, 2 per thread
#pragma unroll
        for (int t = 0; t < 2; t++) {
            int idx = tid + t * 256;
            int r = idx >> 2, kc = (idx & 3) << 2;
            float4 a = make_float4(0.f, 0.f, 0.f, 0.f);
            if (rowBase + r < n)
                a = *(const float4*)(A + (size_t)(rowBase + r) * K + k0 + kc);
            *(float4*)(&As[r][kc]) = a;
        }
        // B tile: 16x128 floats = 512 float4, 2 per thread
#pragma unroll
        for (int t = 0; t < 2; t++) {
            int idx = tid + t * 256;
            int r = idx >> 5, c = (idx & 31) << 2;
            *(float4*)(&Bs[r][c]) =
                *(const float4*)(B + (size_t)(k0 + r) * M + colBase + c);
        }
        __syncthreads();

#pragma unroll
        for (int kk = 0; kk < BK; kk += 8) {
            wmma::fragment<wmma::matrix_a, 16, 16, 8, wmma::precision::tf32,
                           wmma::row_major> af[4];
            wmma::fragment<wmma::matrix_b, 16, 16, 8, wmma::precision::tf32,
                           wmma::row_major> bf[2];
#pragma unroll
            for (int mi = 0; mi < 4; mi++) {
                wmma::load_matrix_sync(af[mi], &As[wr * 64 + mi * 16][kk], BK + 4);
#pragma unroll
                for (int e = 0; e < af[mi].num_elements; e++)
                    af[mi].x[e] = wmma::__float_to_tf32(af[mi].x[e]);
            }
#pragma unroll
            for (int ni = 0; ni < 2; ni++) {
                wmma::load_matrix_sync(bf[ni], &Bs[kk][wc * 32 + ni * 16], BN + 4);
#pragma unroll
                for (int e = 0; e < bf[ni].num_elements; e++)
                    bf[ni].x[e] = wmma::__float_to_tf32(bf[ni].x[e]);
            }
#pragma unroll
            for (int mi = 0; mi < 4; mi++)
#pragma unroll
                for (int ni = 0; ni < 2; ni++)
                    wmma::mma_sync(acc[mi][ni], af[mi], bf[ni], acc[mi][ni]);
        }
        __syncthreads();
    }

    // ---- epilogue: stage each 16x16 frag through smem, fuse bias/gelu/residual
#pragma unroll
    for (int mi = 0; mi < 4; mi++) {
#pragma unroll
        for (int ni = 0; ni < 2; ni++) {
            wmma::store_matrix_sync(&stage[w][0][0], acc[mi][ni], 20,
                                    wmma::mem_row_major);
            __syncwarp();
            int r = rowBase + wr * 64 + mi * 16 + (lane >> 1);
            int c = colBase + wc * 32 + ni * 16 + (lane & 1) * 8;
            if (r < n) {
                const float* sp = &stage[w][lane >> 1][(lane & 1) * 8];
                float4 b0 = *(const float4*)(bias + c);
                float4 b1 = *(const float4*)(bias + c + 4);
                float bb[8] = {b0.x, b0.y, b0.z, b0.w, b1.x, b1.y, b1.z, b1.w};
                float o[8];
#pragma unroll
                for (int j = 0; j < 8; j++) {
                    float v = sp[j] + bb[j];
                    if (EPI == 1)
                        v = 0.5f * v * (1.f + erff(v * 0.7071067811865476f));
                    o[j] = v;
                }
                if (EPI == 2) {
                    const float4* rp =
                        (const float4*)(res + (size_t)r * M + c);
                    float4 r0 = rp[0], r1 = rp[1];
                    o[0] += r0.x; o[1] += r0.y; o[2] += r0.z; o[3] += r0.w;
                    o[4] += r1.x; o[5] += r1.y; o[6] += r1.z; o[7] += r1.w;
                }
                float4* cp = (float4*)(C + (size_t)r * M + c);
                cp[0] = make_float4(o[0], o[1], o[2], o[3]);
                cp[1] = make_float4(o[4], o[5], o[6], o[7]);
            }
            __syncwarp();
        }
    }
}

// ---------------- sparse k=9 attention: one block per node, one warp per head
__global__ void attn_kernel(const float* __restrict__ q, const float* __restrict__ k,
                            const float* __restrict__ v, const int* __restrict__ idx,
                            float* __restrict__ out, int n)
{
    int node = blockIdx.x;
    int head = threadIdx.x >> 5;
    int lane = threadIdx.x & 31;

    __shared__ int s_idx[9];
    if (threadIdx.x < 9)
        s_idx[threadIdx.x] = (threadIdx.x == 0) ? node : idx[(size_t)node * 8 + threadIdx.x - 1];
    __syncthreads();

    const float2* qp = (const float2*)(q + (size_t)node * DMODEL + head * HD);
    float2 q2 = qp[lane];

    float  sc[9];
    float2 vs[9];
#pragma unroll
    for (int t = 0; t < 9; t++) {
        int r = s_idx[t];
        const float2* kp = (const float2*)(k + (size_t)r * DMODEL + head * HD);
        const float2* vp = (const float2*)(v + (size_t)r * DMODEL + head * HD);
        float2 k2 = kp[lane];
        vs[t] = vp[lane];
        float d = q2.x * k2.x + q2.y * k2.y;
#pragma unroll
        for (int o = 16; o; o >>= 1) d += __shfl_xor_sync(0xffffffffu, d, o);
        sc[t] = d * 0.125f;   // 1/sqrt(64)
    }
    float mx = sc[0];
#pragma unroll
    for (int t = 1; t < 9; t++) mx = fmaxf(mx, sc[t]);
    float w[9], sum = 0.f;
#pragma unroll
    for (int t = 0; t < 9; t++) { w[t] = __expf(sc[t] - mx); sum += w[t]; }
    float inv = 1.f / sum;
    float2 o = make_float2(0.f, 0.f);
#pragma unroll
    for (int t = 0; t < 9; t++) {
        float ww = w[t] * inv;
        o.x += ww * vs[t].x;
        o.y += ww * vs[t].y;
    }
    ((float2*)(out + (size_t)node * DMODEL + head * HD))[lane] = o;
}

// ---------------- launch ----------------
extern "C" void kernel_launch(void* const* d_in, const int* in_sizes, int n_in,
                              void* d_out, int out_size)
{
    const float* x     = (const float*)d_in[0];
    const int*   idx   = (const int*)  d_in[1];
    const float* ln1_g = (const float*)d_in[2];
    const float* ln1_b = (const float*)d_in[3];
    const float* Wq    = (const float*)d_in[4];
    const float* bq    = (const float*)d_in[5];
    const float* Wk    = (const float*)d_in[6];
    const float* bk    = (const float*)d_in[7];
    const float* Wv    = (const float*)d_in[8];
    const float* bv    = (const float*)d_in[9];
    const float* Wo    = (const float*)d_in[10];
    const float* bo    = (const float*)d_in[11];
    const float* ln2_g = (const float*)d_in[12];
    const float* ln2_b = (const float*)d_in[13];
    const float* W1    = (const float*)d_in[14];
    const float* b1    = (const float*)d_in[15];
    const float* W2    = (const float*)d_in[16];
    const float* b2    = (const float*)d_in[17];
    float* out = (float*)d_out;

    int n = in_sizes[0] / DMODEL;

    float *qkv, *xn, *attn;
    cudaGetSymbolAddress((void**)&qkv,  g_qkv);
    cudaGetSymbolAddress((void**)&xn,   g_xn);
    cudaGetSymbolAddress((void**)&attn, g_attn);
    float* qq = qkv;
    float* kk = qkv + (size_t)n * DMODEL;
    float* vv = qkv + (size_t)2 * n * DMODEL;

    dim3 gD(DMODEL / 128, (n + 127) / 128);   // (4, 391)
    dim3 gH(HIDDEN / 128, (n + 127) / 128);   // (12, 391)
    int lnGrid = (n + 7) / 8;

    // 1. LN1
    ln_kernel<<<lnGrid, 256>>>(x, ln1_g, ln1_b, xn, n);
    // 2-4. QKV projections (tf32 tensor cores)
    tf32gemm_kernel<0><<<gD, 256>>>(xn, Wq, bq, nullptr, qq, n, DMODEL, DMODEL);
    tf32gemm_kernel<0><<<gD, 256>>>(xn, Wk, bk, nullptr, kk, n, DMODEL, DMODEL);
    tf32gemm_kernel<0><<<gD, 256>>>(xn, Wv, bv, nullptr, vv, n, DMODEL, DMODEL);
    // 5. sparse attention (self + 8 neighbors), fp32 exact
    attn_kernel<<<n, 256>>>(qq, kk, vv, idx, attn, n);
    // 6. output projection + residual -> x1 (into d_out)
    tf32gemm_kernel<2><<<gD, 256>>>(attn, Wo, bo, x, out, n, DMODEL, DMODEL);
    // 7. LN2
    ln_kernel<<<lnGrid, 256>>>(out, ln2_g, ln2_b, xn, n);
    // 8. MLP up + exact GELU (h reuses qkv buffer)
    tf32gemm_kernel<1><<<gH, 256>>>(xn, W1, b1, nullptr, qkv, n, DMODEL, HIDDEN);
    // 9. MLP down + residual (in-place on d_out)
    tf32gemm_kernel<2><<<gD, 256>>>(qkv, W2, b2, out, out, n, HIDDEN, DMODEL);
}

// round 3
// speedup vs baseline: 1.0414x; 1.0414x over previous
#include <cuda_runtime.h>
#include <mma.h>
#include <math.h>
#include <stdint.h>

using namespace nvcuda;

#define N_NODES 50000
#define DMODEL  512
#define NH      8
#define HD      64
#define HIDDEN  1536

// ---------------- static device scratch (no allocs allowed) ----------------
__device__ float g_qkv[(size_t)3 * N_NODES * DMODEL];   // q,k,v ; reused as MLP h
__device__ float g_xn [(size_t)N_NODES * DMODEL];
__device__ float g_attn[(size_t)N_NODES * DMODEL];
// converted (tf32-rounded) weights: Wq,Wk,Wv,Wo (512x512 each), W1, W2 (512x1536 each)
__device__ float g_w[(size_t)4 * DMODEL * DMODEL + (size_t)2 * DMODEL * HIDDEN];

// ---------------- tf32 RN rounding helper ----------------
__device__ __forceinline__ float to_tf32(float x)
{
    uint32_t u;
    asm("cvt.rna.tf32.f32 %0, %1;" : "=r"(u) : "f"(x));
    return __uint_as_float(u);
}

// ---------------- weight conversion: elementwise fp32 -> tf32-rounded -------
__global__ void cvt_kernel(const float* __restrict__ src, float* __restrict__ dst, int n4)
{
    int i = blockIdx.x * blockDim.x + threadIdx.x;
    if (i >= n4) return;
    float4 v = ((const float4*)src)[i];
    v.x = to_tf32(v.x); v.y = to_tf32(v.y); v.z = to_tf32(v.z); v.w = to_tf32(v.w);
    ((float4*)dst)[i] = v;
}

// ---------------- LayerNorm: one warp per row; output tf32-rounded ----------
__global__ void ln_kernel(const float* __restrict__ x, const float* __restrict__ g,
                          const float* __restrict__ b, float* __restrict__ y, int n)
{
    int row  = blockIdx.x * 8 + (threadIdx.x >> 5);
    int lane = threadIdx.x & 31;
    if (row >= n) return;
    const float4* xp = (const float4*)(x + (size_t)row * DMODEL);
    float4 v[4];
    float s = 0.f, ss = 0.f;
#pragma unroll
    for (int i = 0; i < 4; i++) {
        v[i] = xp[i * 32 + lane];
        s  += v[i].x + v[i].y + v[i].z + v[i].w;
        ss += v[i].x*v[i].x + v[i].y*v[i].y + v[i].z*v[i].z + v[i].w*v[i].w;
    }
#pragma unroll
    for (int o = 16; o; o >>= 1) {
        s  += __shfl_xor_sync(0xffffffffu, s,  o);
        ss += __shfl_xor_sync(0xffffffffu, ss, o);
    }
    float mean = s * (1.f / DMODEL);
    float var  = ss * (1.f / DMODEL) - mean * mean;
    float rs   = rsqrtf(var + 1e-5f);
    float4* yp = (float4*)(y + (size_t)row * DMODEL);
    const float4* gp = (const float4*)g;
    const float4* bp = (const float4*)b;
#pragma unroll
    for (int i = 0; i < 4; i++) {
        int c = i * 32 + lane;
        float4 gg = gp[c], bb = bp[c], xx = v[i], o4;
        o4.x = to_tf32((xx.x - mean) * rs * gg.x + bb.x);
        o4.y = to_tf32((xx.y - mean) * rs * gg.y + bb.y);
        o4.z = to_tf32((xx.z - mean) * rs * gg.z + bb.z);
        o4.w = to_tf32((xx.w - mean) * rs * gg.w + bb.w);
        yp[c] = o4;
    }
}

// ---------------- cp.async helpers ----------------
__device__ __forceinline__ void cp16(uint32_t dst, const float* src, int sz)
{
    asm volatile("cp.async.cg.shared.global [%0], [%1], 16, %2;\n"
                 :: "r"(dst), "l"(src), "r"(sz));
}
__device__ __forceinline__ void cp_commit()
{
    asm volatile("cp.async.commit_group;\n" ::);
}
__device__ __forceinline__ void cp_wait0()
{
    asm volatile("cp.async.wait_group 0;\n" ::);
}

// ---------------- TF32 tensor-core GEMM, double-buffered cp.async -----------
// C[n,M] = A[n,K] @ B[K,M] + bias (+epi). A and B are ALREADY tf32-rounded.
// Tiles: 128x128 block, BK=32; 8 warps (2x4), warp tile 64x32 (4x2 wmma frags).
// EPI: 0 = bias only, 1 = gelu(bias) then tf32-round, 2 = bias + residual.
// Dynamic smem layout (floats):
//   As[2] @ 0 / 4608   : 128 x 36 (pad 4)
//   Bs[2] @ 9216/13440 : 32 x 132 (pad 4)
// total 17664 floats = 70656 bytes. Epilogue stage overlays smem[0..2559].
template<int EPI>
__global__ void __launch_bounds__(256)
gemm_tc(const float* __restrict__ A, const float* __restrict__ B,
        const float* __restrict__ bias, const float* __restrict__ res,
        float* __restrict__ C, int n, int K, int M)
{
    extern __shared__ float smem[];
    const uint32_t sbase = (uint32_t)__cvta_generic_to_shared(smem);

    int tid  = threadIdx.x;
    int w    = tid >> 5, lane = tid & 31;
    int wr   = w >> 2,   wc   = w & 3;          // warps: 2 rows x 4 cols
    int rowBase = blockIdx.y * 128;
    int colBase = blockIdx.x * 128;

    wmma::fragment<wmma::accumulator, 16, 16, 8, float> acc[4][2];
#pragma unroll
    for (int i = 0; i < 4; i++)
#pragma unroll
        for (int j = 0; j < 2; j++) wmma::fill_fragment(acc[i][j], 0.f);

    // tile loader: A 128x32 (8 float4 per row), B 32x128 (32 float4 per row)
    auto load_tiles = [&](int buf, int k0) {
#pragma unroll
        for (int t = 0; t < 4; t++) {
            int id = tid + t * 256;
            int r = id >> 3, seg = (id & 7) << 2;
            const float* src = A + (size_t)(rowBase + r) * K + k0 + seg;
            uint32_t dst = sbase + (buf * 4608 + r * 36 + seg) * 4;
            cp16(dst, src, (rowBase + r) < n ? 16 : 0);
        }
#pragma unroll
        for (int t = 0; t < 4; t++) {
            int id = tid + t * 256;
            int r = id >> 5, seg = (id & 31) << 2;
            const float* src = B + (size_t)(k0 + r) * M + colBase + seg;
            uint32_t dst = sbase + (9216 + buf * 4224 + r * 132 + seg) * 4;
            cp16(dst, src, 16);
        }
        cp_commit();
    };

    int nIter = K >> 5;
    load_tiles(0, 0);

    for (int it = 0; it < nIter; it++) {
        cp_wait0();
        __syncthreads();
        if (it + 1 < nIter) load_tiles((it + 1) & 1, (it + 1) << 5);

        const float* As = smem + (it & 1) * 4608;
        const float* Bs = smem + 9216 + (it & 1) * 4224;
#pragma unroll
        for (int kk = 0; kk < 32; kk += 8) {
            wmma::fragment<wmma::matrix_a, 16, 16, 8, wmma::precision::tf32,
                           wmma::row_major> af[4];
            wmma::fragment<wmma::matrix_b, 16, 16, 8, wmma::precision::tf32,
                           wmma::row_major> bf[2];
#pragma unroll
            for (int mi = 0; mi < 4; mi++)
                wmma::load_matrix_sync(af[mi], As + (wr * 64 + mi * 16) * 36 + kk, 36);
#pragma unroll
            for (int ni = 0; ni < 2; ni++)
                wmma::load_matrix_sync(bf[ni], Bs + kk * 132 + wc * 32 + ni * 16, 132);
#pragma unroll
            for (int mi = 0; mi < 4; mi++)
#pragma unroll
                for (int ni = 0; ni < 2; ni++)
                    wmma::mma_sync(acc[mi][ni], af[mi], bf[ni], acc[mi][ni]);
        }
        __syncthreads();
    }

    // ---- epilogue: stage each 16x16 frag through smem ----
    float* stage = smem + w * 320;          // [16][20] per warp
#pragma unroll
    for (int mi = 0; mi < 4; mi++) {
#pragma unroll
        for (int ni = 0; ni < 2; ni++) {
            wmma::store_matrix_sync(stage, acc[mi][ni], 20, wmma::mem_row_major);
            __syncwarp();
            int r = rowBase + wr * 64 + mi * 16 + (lane >> 1);
            int c = colBase + wc * 32 + ni * 16 + (lane & 1) * 8;
            if (r < n) {
                const float* sp = stage + (lane >> 1) * 20 + (lane & 1) * 8;
                float4 b0 = *(const float4*)(bias + c);
                float4 b1 = *(const float4*)(bias + c + 4);
                float bb[8] = {b0.x, b0.y, b0.z, b0.w, b1.x, b1.y, b1.z, b1.w};
                float o[8];
#pragma unroll
                for (int j = 0; j < 8; j++) {
                    float v = sp[j] + bb[j];
                    if (EPI == 1) {
                        v = 0.5f * v * (1.f + erff(v * 0.7071067811865476f));
                        v = to_tf32(v);   // h feeds W2 GEMM as A operand
                    }
                    o[j] = v;
                }
                if (EPI == 2) {
                    const float4* rp = (const float4*)(res + (size_t)r * M + c);
                    float4 r0 = rp[0], r1 = rp[1];
                    o[0] += r0.x; o[1] += r0.y; o[2] += r0.z; o[3] += r0.w;
                    o[4] += r1.x; o[5] += r1.y; o[6] += r1.z; o[7] += r1.w;
                }
                float4* cp = (float4*)(C + (size_t)r * M + c);
                cp[0] = make_float4(o[0], o[1], o[2], o[3]);
                cp[1] = make_float4(o[4], o[5], o[6], o[7]);
            }
            __syncwarp();
        }
    }
}

// ---------------- sparse k=9 attention: one block/node, one warp/head -------
// output tf32-rounded (feeds Wo GEMM as A operand)
__global__ void attn_kernel(const float* __restrict__ q, const float* __restrict__ k,
                            const float* __restrict__ v, const int* __restrict__ idx,
                            float* __restrict__ out, int n)
{
    int node = blockIdx.x;
    int head = threadIdx.x >> 5;
    int lane = threadIdx.x & 31;

    __shared__ int s_idx[9];
    if (threadIdx.x < 9)
        s_idx[threadIdx.x] = (threadIdx.x == 0) ? node : idx[(size_t)node * 8 + threadIdx.x - 1];
    __syncthreads();

    const float2* qp = (const float2*)(q + (size_t)node * DMODEL + head * HD);
    float2 q2 = qp[lane];

    float  sc[9];
    float2 vs[9];
#pragma unroll
    for (int t = 0; t < 9; t++) {
        int r = s_idx[t];
        const float2* kp = (const float2*)(k + (size_t)r * DMODEL + head * HD);
        const float2* vp = (const float2*)(v + (size_t)r * DMODEL + head * HD);
        float2 k2 = kp[lane];
        vs[t] = vp[lane];
        float d = q2.x * k2.x + q2.y * k2.y;
#pragma unroll
        for (int o = 16; o; o >>= 1) d += __shfl_xor_sync(0xffffffffu, d, o);
        sc[t] = d * 0.125f;   // 1/sqrt(64)
    }
    float mx = sc[0];
#pragma unroll
    for (int t = 1; t < 9; t++) mx = fmaxf(mx, sc[t]);
    float w[9], sum = 0.f;
#pragma unroll
    for (int t = 0; t < 9; t++) { w[t] = __expf(sc[t] - mx); sum += w[t]; }
    float inv = 1.f / sum;
    float2 o = make_float2(0.f, 0.f);
#pragma unroll
    for (int t = 0; t < 9; t++) {
        float ww = w[t] * inv;
        o.x += ww * vs[t].x;
        o.y += ww * vs[t].y;
    }
    o.x = to_tf32(o.x);
    o.y = to_tf32(o.y);
    ((float2*)(out + (size_t)node * DMODEL + head * HD))[lane] = o;
}

// ---------------- launch ----------------
extern "C" void kernel_launch(void* const* d_in, const int* in_sizes, int n_in,
                              void* d_out, int out_size)
{
    const float* x     = (const float*)d_in[0];
    const int*   idx   = (const int*)  d_in[1];
    const float* ln1_g = (const float*)d_in[2];
    const float* ln1_b = (const float*)d_in[3];
    const float* Wq    = (const float*)d_in[4];
    const float* bq    = (const float*)d_in[5];
    const float* Wk    = (const float*)d_in[6];
    const float* bk    = (const float*)d_in[7];
    const float* Wv    = (const float*)d_in[8];
    const float* bv    = (const float*)d_in[9];
    const float* Wo    = (const float*)d_in[10];
    const float* bo    = (const float*)d_in[11];
    const float* ln2_g = (const float*)d_in[12];
    const float* ln2_b = (const float*)d_in[13];
    const float* W1    = (const float*)d_in[14];
    const float* b1    = (const float*)d_in[15];
    const float* W2    = (const float*)d_in[16];
    const float* b2    = (const float*)d_in[17];
    float* out = (float*)d_out;

    int n = in_sizes[0] / DMODEL;

    float *qkv, *xn, *attn, *wbuf;
    cudaGetSymbolAddress((void**)&qkv,  g_qkv);
    cudaGetSymbolAddress((void**)&xn,   g_xn);
    cudaGetSymbolAddress((void**)&attn, g_attn);
    cudaGetSymbolAddress((void**)&wbuf, g_w);
    float* qq = qkv;
    float* kk = qkv + (size_t)n * DMODEL;
    float* vv = qkv + (size_t)2 * n * DMODEL;

    const size_t SD = (size_t)DMODEL * DMODEL;   // 262144
    const size_t SH = (size_t)DMODEL * HIDDEN;   // 786432
    float* cWq = wbuf;
    float* cWk = wbuf + SD;
    float* cWv = wbuf + 2 * SD;
    float* cWo = wbuf + 3 * SD;
    float* cW1 = wbuf + 4 * SD;
    float* cW2 = wbuf + 4 * SD + SH;

    const int SMEM = 70656;
    cudaFuncSetAttribute(gemm_tc<0>, cudaFuncAttributeMaxDynamicSharedMemorySize, SMEM);
    cudaFuncSetAttribute(gemm_tc<1>, cudaFuncAttributeMaxDynamicSharedMemorySize, SMEM);
    cudaFuncSetAttribute(gemm_tc<2>, cudaFuncAttributeMaxDynamicSharedMemorySize, SMEM);

    dim3 gD(DMODEL / 128, (n + 127) / 128);   // (4, 391)
    dim3 gH(HIDDEN / 128, (n + 127) / 128);   // (12, 391)
    int lnGrid = (n + 7) / 8;

    // 0. weight conversion (tf32 RN rounding), ~10us total
    cvt_kernel<<<(int)(SD / 4 + 255) / 256, 256>>>(Wq, cWq, (int)(SD / 4));
    cvt_kernel<<<(int)(SD / 4 + 255) / 256, 256>>>(Wk, cWk, (int)(SD / 4));
    cvt_kernel<<<(int)(SD / 4 + 255) / 256, 256>>>(Wv, cWv, (int)(SD / 4));
    cvt_kernel<<<(int)(SD / 4 + 255) / 256, 256>>>(Wo, cWo, (int)(SD / 4));
    cvt_kernel<<<(int)(SH / 4 + 255) / 256, 256>>>(W1, cW1, (int)(SH / 4));
    cvt_kernel<<<(int)(SH / 4 + 255) / 256, 256>>>(W2, cW2, (int)(SH / 4));

    // 1. LN1 (tf32-rounded output)
    ln_kernel<<<lnGrid, 256>>>(x, ln1_g, ln1_b, xn, n);
    // 2-4. QKV projections
    gemm_tc<0><<<gD, 256, SMEM>>>(xn, cWq, bq, nullptr, qq, n, DMODEL, DMODEL);
    gemm_tc<0><<<gD, 256, SMEM>>>(xn, cWk, bk, nullptr, kk, n, DMODEL, DMODEL);
    gemm_tc<0><<<gD, 256, SMEM>>>(xn, cWv, bv, nullptr, vv, n, DMODEL, DMODEL);
    // 5. sparse attention (self + 8 neighbors), fp32 math, tf32-rounded out
    attn_kernel<<<n, 256>>>(qq, kk, vv, idx, attn, n);
    // 6. output projection + residual -> x1 (into d_out, exact fp32)
    gemm_tc<2><<<gD, 256, SMEM>>>(attn, cWo, bo, x, out, n, DMODEL, DMODEL);
    // 7. LN2 (tf32-rounded output)
    ln_kernel<<<lnGrid, 256>>>(out, ln2_g, ln2_b, xn, n);
    // 8. MLP up + exact GELU (h reuses qkv buffer, tf32-rounded)
    gemm_tc<1><<<gH, 256, SMEM>>>(xn, cW1, b1, nullptr, qkv, n, DMODEL, HIDDEN);
    // 9. MLP down + residual (in-place on d_out, exact fp32)
    gemm_tc<2><<<gD, 256, SMEM>>>(qkv, cW2, b2, out, out, n, HIDDEN, DMODEL);
}